// round 1
// baseline (speedup 1.0000x reference)
#include <cuda_runtime.h>
#include <math.h>

#define BSZ 64
#define MM  2048
#define DD  1024
#define HH  1024
#define HT  8            // H / 128 tiles

#define BM 128
#define BN 128
#define BK 16

// Scratch (device globals: allocation-free rule)
__device__ float g_qproj[BSZ * HH];          // 256 KB
__device__ float g_part[HT * BSZ * MM];      // 4 MB: per-hTile partial attn logits

// ---------------------------------------------------------------------------
// Kernel 1: q_proj[b,h] = query[b,:] . Wq[h,:] + bq[h]
// grid (BSZ, HH/128), block 128 (4 warps, one h per warp per step)
// ---------------------------------------------------------------------------
__global__ __launch_bounds__(128) void qproj_kernel(
    const float* __restrict__ query,
    const float* __restrict__ Wq,
    const float* __restrict__ bq)
{
    __shared__ float qs[DD];
    const int b  = blockIdx.x;
    const int h0 = blockIdx.y * 128;
    const int tid = threadIdx.x;

    for (int i = tid; i < DD; i += 128) qs[i] = query[b * DD + i];
    __syncthreads();

    const int warp = tid >> 5, lane = tid & 31;
    for (int hl = warp; hl < 128; hl += 4) {
        const int h = h0 + hl;
        const float* w = Wq + (size_t)h * DD;
        float s = 0.f;
        #pragma unroll 8
        for (int j = lane; j < DD; j += 32) s += qs[j] * w[j];
        #pragma unroll
        for (int off = 16; off > 0; off >>= 1)
            s += __shfl_xor_sync(0xffffffffu, s, off);
        if (lane == 0) g_qproj[b * HH + h] = s + bq[h];
    }
}

// ---------------------------------------------------------------------------
// Kernel 2: fused  m_proj GEMM + tanh + dot(v)  -> g_part[hTile][row]
//   C[row,h] = sum_d memory[row,d] * Wm[h,d]
//   partial_attn[row] += sum_h tanh(C + qproj[b,h]) * v[h]   (h in this tile)
// 128x128 tile, BK=16, 256 threads, 8x8 microtile.
// ---------------------------------------------------------------------------
__global__ __launch_bounds__(256) void fused_attn_gemm_kernel(
    const float* __restrict__ A,    // memory [BSZ*MM, DD]
    const float* __restrict__ B,    // Wm     [HH, DD]
    const float* __restrict__ v)    // [HH]
{
    __shared__ float As[BK * BM];       // transposed: As[k][row]
    __shared__ float Bs[BK * BN];       // transposed: Bs[k][h]
    __shared__ float red[BM * 16];

    const int tid = threadIdx.x;
    const int ty = tid >> 4;            // 0..15
    const int tx = tid & 15;            // 0..15
    const int row0 = blockIdx.y * BM;
    const int h0   = blockIdx.x * BN;

    const int lr = tid >> 2;            // 0..63  (load row)
    const int lc = (tid & 3) * 4;       // 0,4,8,12 (load col group)

    const float* Ab = A + (size_t)row0 * DD;
    const float* Bb = B + (size_t)h0 * DD;

    float acc[8][8];
    #pragma unroll
    for (int i = 0; i < 8; i++)
        #pragma unroll
        for (int j = 0; j < 8; j++) acc[i][j] = 0.f;

    for (int k0 = 0; k0 < DD; k0 += BK) {
        // stage global loads into registers
        const float4 a0 = *(const float4*)(Ab + (size_t)lr        * DD + k0 + lc);
        const float4 a1 = *(const float4*)(Ab + (size_t)(lr + 64) * DD + k0 + lc);
        const float4 b0 = *(const float4*)(Bb + (size_t)lr        * DD + k0 + lc);
        const float4 b1 = *(const float4*)(Bb + (size_t)(lr + 64) * DD + k0 + lc);

        __syncthreads();   // previous tile's compute done
        As[(lc + 0) * BM + lr] = a0.x;  As[(lc + 1) * BM + lr] = a0.y;
        As[(lc + 2) * BM + lr] = a0.z;  As[(lc + 3) * BM + lr] = a0.w;
        As[(lc + 0) * BM + lr + 64] = a1.x;  As[(lc + 1) * BM + lr + 64] = a1.y;
        As[(lc + 2) * BM + lr + 64] = a1.z;  As[(lc + 3) * BM + lr + 64] = a1.w;
        Bs[(lc + 0) * BN + lr] = b0.x;  Bs[(lc + 1) * BN + lr] = b0.y;
        Bs[(lc + 2) * BN + lr] = b0.z;  Bs[(lc + 3) * BN + lr] = b0.w;
        Bs[(lc + 0) * BN + lr + 64] = b1.x;  Bs[(lc + 1) * BN + lr + 64] = b1.y;
        Bs[(lc + 2) * BN + lr + 64] = b1.z;  Bs[(lc + 3) * BN + lr + 64] = b1.w;
        __syncthreads();

        #pragma unroll
        for (int kk = 0; kk < BK; kk++) {
            float af[8], bf[8];
            float4 av0 = *(const float4*)&As[kk * BM + ty * 8];
            float4 av1 = *(const float4*)&As[kk * BM + ty * 8 + 4];
            float4 bv0 = *(const float4*)&Bs[kk * BN + tx * 8];
            float4 bv1 = *(const float4*)&Bs[kk * BN + tx * 8 + 4];
            af[0]=av0.x; af[1]=av0.y; af[2]=av0.z; af[3]=av0.w;
            af[4]=av1.x; af[5]=av1.y; af[6]=av1.z; af[7]=av1.w;
            bf[0]=bv0.x; bf[1]=bv0.y; bf[2]=bv0.z; bf[3]=bv0.w;
            bf[4]=bv1.x; bf[5]=bv1.y; bf[6]=bv1.z; bf[7]=bv1.w;
            #pragma unroll
            for (int i = 0; i < 8; i++)
                #pragma unroll
                for (int j = 0; j < 8; j++)
                    acc[i][j] += af[i] * bf[j];
        }
    }

    // Epilogue: tanh(acc + qproj) . v  -> per-row partial
    const int batch = row0 >> 11;      // row0 / MM, MM = 2048
    float qp[8], vv[8];
    #pragma unroll
    for (int j = 0; j < 8; j++) {
        const int h = h0 + tx * 8 + j;
        qp[j] = g_qproj[batch * HH + h];
        vv[j] = v[h];
    }
    __syncthreads();   // done with As/Bs usage pattern; safe before red writes
    #pragma unroll
    for (int i = 0; i < 8; i++) {
        float p = 0.f;
        #pragma unroll
        for (int j = 0; j < 8; j++)
            p += tanhf(acc[i][j] + qp[j]) * vv[j];
        red[(ty * 8 + i) * 16 + tx] = p;
    }
    __syncthreads();
    if (tid < BM) {
        float s = 0.f;
        #pragma unroll
        for (int t = 0; t < 16; t++) s += red[tid * 16 + t];
        g_part[blockIdx.x * (BSZ * MM) + row0 + tid] = s;
    }
}

// ---------------------------------------------------------------------------
// Kernel 3: sum h-tile partials, softmax over M per batch -> weights (d_out)
// ---------------------------------------------------------------------------
__global__ __launch_bounds__(256) void softmax_kernel(float* __restrict__ out_w)
{
    __shared__ float sm[MM];
    __shared__ float red[256];
    const int b = blockIdx.x, tid = threadIdx.x;

    float lmax = -1e30f;
    for (int m = tid; m < MM; m += 256) {
        float s = 0.f;
        #pragma unroll
        for (int t = 0; t < HT; t++) s += g_part[t * (BSZ * MM) + b * MM + m];
        sm[m] = s;
        lmax = fmaxf(lmax, s);
    }
    red[tid] = lmax; __syncthreads();
    for (int off = 128; off > 0; off >>= 1) {
        if (tid < off) red[tid] = fmaxf(red[tid], red[tid + off]);
        __syncthreads();
    }
    const float mx = red[0];
    __syncthreads();

    float lsum = 0.f;
    for (int m = tid; m < MM; m += 256) {
        const float e = expf(sm[m] - mx);
        sm[m] = e;
        lsum += e;
    }
    red[tid] = lsum; __syncthreads();
    for (int off = 128; off > 0; off >>= 1) {
        if (tid < off) red[tid] += red[tid + off];
        __syncthreads();
    }
    const float inv = 1.f / red[0];
    for (int m = tid; m < MM; m += 256)
        out_w[b * MM + m] = sm[m] * inv;
}

// ---------------------------------------------------------------------------
// Kernel 4: weighted_memory[b,d] = sum_m w[b,m] * memory[b,m,d]
// grid (DD/128, BSZ), 256 threads = 128 d-lanes x 2 m-groups
// ---------------------------------------------------------------------------
__global__ __launch_bounds__(256) void weighted_mem_kernel(
    const float* __restrict__ mem,
    const float* __restrict__ weights,
    float* __restrict__ out_wm)
{
    __shared__ float wsh[MM];
    __shared__ float red[256];
    const int b = blockIdx.y;
    const int d0 = blockIdx.x * 128;
    const int tid = threadIdx.x;

    for (int i = tid; i < MM; i += 256) wsh[i] = weights[b * MM + i];
    __syncthreads();

    const int dl = tid & 127;
    const int grp = tid >> 7;
    const int d = d0 + dl;

    float acc = 0.f;
    for (int m = grp; m < MM; m += 2)
        acc += wsh[m] * mem[((size_t)(b * MM + m)) * DD + d];

    red[tid] = acc; __syncthreads();
    if (tid < 128)
        out_wm[b * DD + d] = red[tid] + red[tid + 128];
}

// ---------------------------------------------------------------------------
extern "C" void kernel_launch(void* const* d_in, const int* in_sizes, int n_in,
                              void* d_out, int out_size)
{
    const float* query  = (const float*)d_in[0];
    const float* memory = (const float*)d_in[1];
    const float* Wq     = (const float*)d_in[2];
    const float* bq     = (const float*)d_in[3];
    const float* Wm     = (const float*)d_in[4];
    const float* v      = (const float*)d_in[5];
    float* out = (float*)d_out;

    float* out_weights = out;                  // [BSZ, 1, MM]
    float* out_wmem    = out + BSZ * MM;       // [BSZ, 1, DD]

    qproj_kernel<<<dim3(BSZ, HH / 128), 128>>>(query, Wq, bq);
    fused_attn_gemm_kernel<<<dim3(HH / BN, (BSZ * MM) / BM), 256>>>(memory, Wm, v);
    softmax_kernel<<<BSZ, 256>>>(out_weights);
    weighted_mem_kernel<<<dim3(DD / 128, BSZ), 256>>>(memory, out_weights, out_wmem);
}